// round 1
// baseline (speedup 1.0000x reference)
#include <cuda_runtime.h>

#define N_CUST 100000
#define N_PROD 10000
#define DD 128
#define HH 128
#define OUTD 64
#define NREL 5

// ------------------------- device scratch (no allocs allowed) -------------------------
__device__ float g_wsvec[128];            // Ws_gat @ a_s
__device__ float g_wdvec[128];            // Wd_gat @ a_d
__device__ float g_bias[128];             // sum of 5 branch biases
__device__ float g_wrsum[128 * 128];      // Wr_to + Wr_from + Wr_div
__device__ float g_ls[N_CUST];
__device__ float g_ld[N_PROD];
__device__ int   g_deg_s[N_CUST];         // purchase src degree
__device__ int   g_counts[NREL][N_PROD];
__device__ int   g_offsets[NREL][N_PROD + 1];
__device__ int   g_cursor[NREL][N_PROD];
__device__ int   g_sorted[NREL][500000];
__device__ float g_feat[NREL][N_PROD * 128];  // 0:gcn 1:gat 2:mean_to 3:mean_from 4:mean_div
__device__ float g_relu[N_PROD * 128];

// ------------------------- utility kernels -------------------------
__global__ void zero_kernel() {
    int n = N_CUST + NREL * N_PROD;
    for (int i = blockIdx.x * blockDim.x + threadIdx.x; i < n; i += gridDim.x * blockDim.x) {
        if (i < N_CUST) g_deg_s[i] = 0;
        else ((int*)g_counts)[i - N_CUST] = 0;
    }
}

__global__ void prep_kernel(const float* __restrict__ Ws, const float* __restrict__ Wd,
                            const float* __restrict__ a_s, const float* __restrict__ a_d,
                            const float* __restrict__ bg, const float* __restrict__ bgat,
                            const float* __restrict__ bto, const float* __restrict__ bfrom,
                            const float* __restrict__ bdiv,
                            const float* __restrict__ Wrt, const float* __restrict__ Wrf,
                            const float* __restrict__ Wrd) {
    if (blockIdx.x == 0) {
        int t = threadIdx.x;
        if (t < 128) {
            float s1 = 0.f, s2 = 0.f;
            for (int j = 0; j < 128; j++) {
                s1 += Ws[t * 128 + j] * a_s[j];
                s2 += Wd[t * 128 + j] * a_d[j];
            }
            g_wsvec[t] = s1;
            g_wdvec[t] = s2;
            g_bias[t] = bg[t] + bgat[t] + bto[t] + bfrom[t] + bdiv[t];
        }
    } else {
        int i = (blockIdx.x - 1) * blockDim.x + threadIdx.x;
        if (i < 128 * 128) g_wrsum[i] = Wrt[i] + Wrf[i] + Wrd[i];
    }
}

// ls / ld: per-row dot with a 128-vector. One warp per row.
__global__ void rowdot_kernel(const float* __restrict__ x, int nrows, int which) {
    int gw = (blockIdx.x * blockDim.x + threadIdx.x) >> 5;
    int lane = threadIdx.x & 31;
    if (gw >= nrows) return;
    const float* vec = which ? g_wdvec : g_wsvec;
    float4 wv = ((const float4*)vec)[lane];
    float4 xv = ((const float4*)x)[gw * 32 + lane];
    float d = xv.x * wv.x + xv.y * wv.y + xv.z * wv.z + xv.w * wv.w;
#pragma unroll
    for (int o = 16; o; o >>= 1) d += __shfl_xor_sync(0xffffffffu, d, o);
    if (lane == 0) {
        if (which) g_ld[gw] = d; else g_ls[gw] = d;
    }
}

__global__ void hist_kernel(const int* __restrict__ idx, int n, int rel) {
    int* bins;
    if (rel < 0) bins = g_deg_s; else bins = g_counts[rel];
    for (int i = blockIdx.x * blockDim.x + threadIdx.x; i < n; i += gridDim.x * blockDim.x)
        atomicAdd(&bins[idx[i]], 1);
}

// single-block exclusive scan over 10000 counts -> offsets & cursor
__global__ void scan_kernel(int rel) {
    __shared__ int sbuf[1024];
    __shared__ int s_carry;
    int tid = threadIdx.x;
    if (tid == 0) s_carry = 0;
    __syncthreads();
    const int* cnt = g_counts[rel];
    int* off = g_offsets[rel];
    int* cur = g_cursor[rel];
    for (int c = 0; c < 10; c++) {
        int i = c * 1024 + tid;
        int v = (i < N_PROD) ? cnt[i] : 0;
        sbuf[tid] = v;
        __syncthreads();
        for (int d = 1; d < 1024; d <<= 1) {
            int t = (tid >= d) ? sbuf[tid - d] : 0;
            __syncthreads();
            sbuf[tid] += t;
            __syncthreads();
        }
        int incl = sbuf[tid];
        int carry = s_carry;
        if (i < N_PROD) {
            int excl = carry + incl - v;
            off[i] = excl;
            cur[i] = excl;
        }
        int tot = sbuf[1023];
        __syncthreads();
        if (tid == 0) s_carry = carry + tot;
        __syncthreads();
    }
    if (tid == 0) off[N_PROD] = s_carry;
}

__global__ void scatter_kernel(const int* __restrict__ src, const int* __restrict__ dst,
                               int n, int rel) {
    int* cur = g_cursor[rel];
    int* srt = g_sorted[rel];
    for (int i = blockIdx.x * blockDim.x + threadIdx.x; i < n; i += gridDim.x * blockDim.x) {
        int d = dst[i];
        int p = atomicAdd(&cur[d], 1);
        srt[p] = src[i];
    }
}

// ------------------------- aggregation: one warp per dst row -------------------------
__global__ void sage_agg_kernel(const float* __restrict__ x, int rel) {
    int gw = (blockIdx.x * blockDim.x + threadIdx.x) >> 5;
    if (gw >= N_PROD) return;
    int lane = threadIdx.x & 31;
    const int* off = g_offsets[rel];
    const int* srt = g_sorted[rel];
    int o0 = off[gw], o1 = off[gw + 1];
    const float4* x4 = (const float4*)x;
    float4 a = make_float4(0.f, 0.f, 0.f, 0.f);
    int e = o0;
    for (; e + 1 < o1; e += 2) {
        int s0 = srt[e], s1 = srt[e + 1];
        float4 v0 = x4[s0 * 32 + lane];
        float4 v1 = x4[s1 * 32 + lane];
        a.x += v0.x + v1.x; a.y += v0.y + v1.y; a.z += v0.z + v1.z; a.w += v0.w + v1.w;
    }
    if (e < o1) {
        int s0 = srt[e];
        float4 v0 = x4[s0 * 32 + lane];
        a.x += v0.x; a.y += v0.y; a.z += v0.z; a.w += v0.w;
    }
    int c = o1 - o0; if (c < 1) c = 1;
    float inv = 1.0f / (float)c;
    a.x *= inv; a.y *= inv; a.z *= inv; a.w *= inv;
    ((float4*)g_feat[rel])[gw * 32 + lane] = a;
}

__global__ void gcn_agg_kernel(const float* __restrict__ x) {
    int gw = (blockIdx.x * blockDim.x + threadIdx.x) >> 5;
    if (gw >= N_PROD) return;
    int lane = threadIdx.x & 31;
    const int* off = g_offsets[0];
    const int* srt = g_sorted[0];
    int o0 = off[gw], o1 = off[gw + 1];
    float dd = (float)(o1 - o0);
    const float4* x4 = (const float4*)x;
    float4 a = make_float4(0.f, 0.f, 0.f, 0.f);
    for (int e = o0; e < o1; e++) {
        int s = srt[e];
        float nrm = rsqrtf((float)g_deg_s[s] * dd);
        float4 v = x4[s * 32 + lane];
        a.x += nrm * v.x; a.y += nrm * v.y; a.z += nrm * v.z; a.w += nrm * v.w;
    }
    ((float4*)g_feat[0])[gw * 32 + lane] = a;
}

__global__ void gat_agg_kernel(const float* __restrict__ x) {
    int gw = (blockIdx.x * blockDim.x + threadIdx.x) >> 5;
    if (gw >= N_PROD) return;
    int lane = threadIdx.x & 31;
    const int* off = g_offsets[1];
    const int* srt = g_sorted[1];
    int o0 = off[gw], o1 = off[gw + 1];
    const float4* x4 = (const float4*)x;
    float4 a = make_float4(0.f, 0.f, 0.f, 0.f);
    if (o0 < o1) {
        float ldv = g_ld[gw];
        // pass 1: segment max of leaky_relu(ls[s] + ld[d]) — lanes stride edges
        float m = -1e30f;
        for (int e = o0 + lane; e < o1; e += 32) {
            int s = srt[e];
            float l = g_ls[s] + ldv;
            l = (l > 0.f) ? l : 0.2f * l;
            m = fmaxf(m, l);
        }
#pragma unroll
        for (int o = 16; o; o >>= 1) m = fmaxf(m, __shfl_xor_sync(0xffffffffu, m, o));
        // pass 2: weighted accumulate (den identical across lanes)
        float den = 0.f;
        for (int e = o0; e < o1; e++) {
            int s = srt[e];
            float l = g_ls[s] + ldv;
            l = (l > 0.f) ? l : 0.2f * l;
            float w = __expf(l - m);
            den += w;
            float4 v = x4[s * 32 + lane];
            a.x += w * v.x; a.y += w * v.y; a.z += w * v.z; a.w += w * v.w;
        }
        float inv = 1.0f / den;
        a.x *= inv; a.y *= inv; a.z *= inv; a.w *= inv;
    }
    ((float4*)g_feat[1])[gw * 32 + lane] = a;
}

// ------------------------- GEMM stage 1: accum[10000x128] = sum_p S_p @ W_p + bias, relu ---
// K = 6*128 = 768 spread across 6 (A,B) pairs. BM=64, BN=128, BK=16, 256 threads, 4x8 micro.
__global__ void gemm1_kernel(const float* __restrict__ xprod,
                             const float* __restrict__ Wg, const float* __restrict__ Wsg,
                             const float* __restrict__ Wlt, const float* __restrict__ Wlf,
                             const float* __restrict__ Wld) {
    __shared__ float As[16][65];
    __shared__ float Bs[16][128];
    int tid = threadIdx.x;
    int ty = tid >> 4, tx = tid & 15;
    int m0 = blockIdx.x * 64;
    float acc[4][8];
#pragma unroll
    for (int i = 0; i < 4; i++)
#pragma unroll
        for (int j = 0; j < 8; j++) acc[i][j] = 0.f;

    const float* Asrc[6] = {g_feat[0], g_feat[1], g_feat[2], g_feat[3], g_feat[4], xprod};
    const float* Bsrc[6] = {Wg, Wsg, Wlt, Wlf, Wld, g_wrsum};

    for (int p = 0; p < 6; p++) {
        const float* A = Asrc[p];
        const float* B = Bsrc[p];
        for (int kt = 0; kt < 8; kt++) {
            int kc0 = kt * 16;
#pragma unroll
            for (int j = 0; j < 4; j++) {
                int idx = tid + j * 256;
                int m = idx >> 4, kk = idx & 15;
                int row = m0 + m;
                As[kk][m] = (row < N_PROD) ? A[row * 128 + kc0 + kk] : 0.f;
            }
#pragma unroll
            for (int j = 0; j < 8; j++) {
                int idx = tid + j * 256;
                int kk = idx >> 7, n = idx & 127;
                Bs[kk][n] = B[(kc0 + kk) * 128 + n];
            }
            __syncthreads();
#pragma unroll
            for (int kk = 0; kk < 16; kk++) {
                float av[4], bv[8];
#pragma unroll
                for (int i = 0; i < 4; i++) av[i] = As[kk][ty * 4 + i];
#pragma unroll
                for (int j = 0; j < 8; j++) bv[j] = Bs[kk][tx * 8 + j];
#pragma unroll
                for (int i = 0; i < 4; i++)
#pragma unroll
                    for (int j = 0; j < 8; j++) acc[i][j] += av[i] * bv[j];
            }
            __syncthreads();
        }
    }
#pragma unroll
    for (int i = 0; i < 4; i++) {
        int row = m0 + ty * 4 + i;
        if (row < N_PROD) {
#pragma unroll
            for (int j = 0; j < 8; j++) {
                int col = tx * 8 + j;
                float v = acc[i][j] + g_bias[col];
                g_relu[row * 128 + col] = (v > 0.f) ? v : 0.f;
            }
        }
    }
}

// ------------------------- GEMM stage 2: out[10000x64] = g_relu @ W_out + b_out --------
// BM=64, BN=64, BK=16, 256 threads, 4x4 micro.
__global__ void gemm2_kernel(const float* __restrict__ Wout, const float* __restrict__ bout,
                             float* __restrict__ out) {
    __shared__ float As[16][65];
    __shared__ float Bs[16][64];
    int tid = threadIdx.x;
    int ty = tid >> 4, tx = tid & 15;
    int m0 = blockIdx.x * 64;
    float acc[4][4];
#pragma unroll
    for (int i = 0; i < 4; i++)
#pragma unroll
        for (int j = 0; j < 4; j++) acc[i][j] = 0.f;

    for (int kt = 0; kt < 8; kt++) {
        int kc0 = kt * 16;
#pragma unroll
        for (int j = 0; j < 4; j++) {
            int idx = tid + j * 256;
            int m = idx >> 4, kk = idx & 15;
            int row = m0 + m;
            As[kk][m] = (row < N_PROD) ? g_relu[row * 128 + kc0 + kk] : 0.f;
        }
#pragma unroll
        for (int j = 0; j < 4; j++) {
            int idx = tid + j * 256;
            int kk = idx >> 6, n = idx & 63;
            Bs[kk][n] = Wout[(kc0 + kk) * 64 + n];
        }
        __syncthreads();
#pragma unroll
        for (int kk = 0; kk < 16; kk++) {
            float av[4], bv[4];
#pragma unroll
            for (int i = 0; i < 4; i++) av[i] = As[kk][ty * 4 + i];
#pragma unroll
            for (int j = 0; j < 4; j++) bv[j] = Bs[kk][tx * 4 + j];
#pragma unroll
            for (int i = 0; i < 4; i++)
#pragma unroll
                for (int j = 0; j < 4; j++) acc[i][j] += av[i] * bv[j];
        }
        __syncthreads();
    }
#pragma unroll
    for (int i = 0; i < 4; i++) {
        int row = m0 + ty * 4 + i;
        if (row < N_PROD) {
#pragma unroll
            for (int j = 0; j < 4; j++) {
                int col = tx * 4 + j;
                out[row * 64 + col] = acc[i][j] + bout[col];
            }
        }
    }
}

// ------------------------- launch -------------------------
extern "C" void kernel_launch(void* const* d_in, const int* in_sizes, int n_in,
                              void* d_out, int out_size) {
    const float* x_cust = (const float*)d_in[0];
    const float* x_prod = (const float*)d_in[1];
    const int* srcs[NREL];
    const int* dsts[NREL];
    for (int r = 0; r < NREL; r++) {
        srcs[r] = (const int*)d_in[2 + 2 * r];
        dsts[r] = (const int*)d_in[3 + 2 * r];
    }
    const float* W_gcn  = (const float*)d_in[12];
    const float* b_gcn  = (const float*)d_in[13];
    const float* Ws_gat = (const float*)d_in[14];
    const float* Wd_gat = (const float*)d_in[15];
    const float* a_s    = (const float*)d_in[16];
    const float* a_d    = (const float*)d_in[17];
    const float* b_gat  = (const float*)d_in[18];
    const float* Wl_to  = (const float*)d_in[19];
    const float* b_to   = (const float*)d_in[20];
    const float* Wr_to  = (const float*)d_in[21];
    const float* Wl_fr  = (const float*)d_in[22];
    const float* b_fr   = (const float*)d_in[23];
    const float* Wr_fr  = (const float*)d_in[24];
    const float* Wl_dv  = (const float*)d_in[25];
    const float* b_dv   = (const float*)d_in[26];
    const float* Wr_dv  = (const float*)d_in[27];
    const float* W_out  = (const float*)d_in[28];
    const float* b_out  = (const float*)d_in[29];
    int E = in_sizes[2];

    zero_kernel<<<256, 256>>>();
    prep_kernel<<<65, 256>>>(Ws_gat, Wd_gat, a_s, a_d,
                             b_gcn, b_gat, b_to, b_fr, b_dv,
                             Wr_to, Wr_fr, Wr_dv);
    rowdot_kernel<<<(N_CUST + 7) / 8, 256>>>(x_cust, N_CUST, 0);
    rowdot_kernel<<<(N_PROD + 7) / 8, 256>>>(x_prod, N_PROD, 1);

    hist_kernel<<<512, 256>>>(srcs[0], E, -1);  // deg_s over purchase src
    for (int r = 0; r < NREL; r++) hist_kernel<<<512, 256>>>(dsts[r], E, r);
    for (int r = 0; r < NREL; r++) scan_kernel<<<1, 1024>>>(r);
    for (int r = 0; r < NREL; r++) scatter_kernel<<<512, 256>>>(srcs[r], dsts[r], E, r);

    gcn_agg_kernel<<<(N_PROD + 7) / 8, 256>>>(x_cust);
    gat_agg_kernel<<<(N_PROD + 7) / 8, 256>>>(x_cust);
    for (int r = 2; r < 5; r++) sage_agg_kernel<<<(N_PROD + 7) / 8, 256>>>(x_cust, r);

    gemm1_kernel<<<(N_PROD + 63) / 64, 256>>>(x_prod, W_gcn, Ws_gat, Wl_to, Wl_fr, Wl_dv);
    gemm2_kernel<<<(N_PROD + 63) / 64, 256>>>(W_out, b_out, (float*)d_out);
}

// round 2
// speedup vs baseline: 1.3897x; 1.3897x over previous
#include <cuda_runtime.h>

#define N_CUST 100000
#define N_PROD 10000
#define NREL 5
#define EMAX 500000

// ------------------------- device scratch (no allocs allowed) -------------------------
__device__ float g_wsvec[128];            // Ws_gat @ a_s
__device__ float g_wdvec[128];            // Wd_gat @ a_d
__device__ float g_bias[128];             // sum of 5 branch biases
__device__ float g_wrsum[128 * 128];      // Wr_to + Wr_from + Wr_div
__device__ float g_ls[N_CUST];
__device__ float g_ld[N_PROD];
__device__ int   g_deg_s[N_CUST];         // purchase src degree
__device__ int   g_counts[NREL][N_PROD];
__device__ int   g_offsets[NREL][N_PROD + 1];
__device__ int   g_cursor[NREL][N_PROD];
__device__ int   g_sorted[NREL][EMAX];
__device__ float g_feat[NREL][N_PROD * 128];  // 0:gcn 1:gat 2:mean_to 3:mean_from 4:mean_div

struct EdgePtrs {
    const int* src[NREL];
    const int* dst[NREL];
    int E;
};

// ------------------------- setup: zero counters + weight prep, one launch -------------
__global__ void setup_kernel(const float* __restrict__ Ws, const float* __restrict__ Wd,
                             const float* __restrict__ a_s, const float* __restrict__ a_d,
                             const float* __restrict__ bg, const float* __restrict__ bgat,
                             const float* __restrict__ bto, const float* __restrict__ bfrom,
                             const float* __restrict__ bdiv,
                             const float* __restrict__ Wrt, const float* __restrict__ Wrf,
                             const float* __restrict__ Wrd) {
    int b = blockIdx.x;
    if (b == 0) {
        int t = threadIdx.x;
        if (t < 128) {
            float s1 = 0.f, s2 = 0.f;
            for (int j = 0; j < 128; j++) {
                s1 += Ws[t * 128 + j] * a_s[j];
                s2 += Wd[t * 128 + j] * a_d[j];
            }
            g_wsvec[t] = s1;
            g_wdvec[t] = s2;
            g_bias[t] = bg[t] + bgat[t] + bto[t] + bfrom[t] + bdiv[t];
        }
    } else if (b <= 64) {
        int i = (b - 1) * 256 + threadIdx.x;
        g_wrsum[i] = Wrt[i] + Wrf[i] + Wrd[i];
    } else {
        int n = N_CUST + NREL * N_PROD;
        int stride = (gridDim.x - 65) * 256;
        for (int i = (b - 65) * 256 + threadIdx.x; i < n; i += stride) {
            if (i < N_CUST) g_deg_s[i] = 0;
            else ((int*)g_counts)[i - N_CUST] = 0;
        }
    }
}

// ------------------------- ls/ld for both node sets in one launch ---------------------
__global__ void rowdot_all(const float* __restrict__ xc, const float* __restrict__ xp) {
    int gw = (blockIdx.x * blockDim.x + threadIdx.x) >> 5;
    int lane = threadIdx.x & 31;
    if (gw >= N_CUST + N_PROD) return;
    float4 wv, xv;
    if (gw < N_CUST) {
        wv = ((const float4*)g_wsvec)[lane];
        xv = ((const float4*)xc)[gw * 32 + lane];
    } else {
        wv = ((const float4*)g_wdvec)[lane];
        xv = ((const float4*)xp)[(gw - N_CUST) * 32 + lane];
    }
    float d = xv.x * wv.x + xv.y * wv.y + xv.z * wv.z + xv.w * wv.w;
#pragma unroll
    for (int o = 16; o; o >>= 1) d += __shfl_xor_sync(0xffffffffu, d, o);
    if (lane == 0) {
        if (gw < N_CUST) g_ls[gw] = d; else g_ld[gw - N_CUST] = d;
    }
}

// ------------------------- all 6 histograms in one launch (gridDim.y = 6) -------------
__global__ void hist_all(EdgePtrs ep) {
    int y = blockIdx.y;
    const int* idx;
    int* bins;
    if (y == 0) { idx = ep.src[0]; bins = g_deg_s; }
    else        { idx = ep.dst[y - 1]; bins = g_counts[y - 1]; }
    for (int i = blockIdx.x * blockDim.x + threadIdx.x; i < ep.E; i += gridDim.x * blockDim.x)
        atomicAdd(&bins[idx[i]], 1);
}

// ------------------------- 5 parallel block scans (one block per relation) ------------
__global__ void scan_all() {
    int rel = blockIdx.x;
    const int* cnt = g_counts[rel];
    int* off = g_offsets[rel];
    int* cur = g_cursor[rel];
    int tid = threadIdx.x;
    int lane = tid & 31, wid = tid >> 5;
    int base = tid * 10;
    int v[10];
    int s = 0;
#pragma unroll
    for (int i = 0; i < 10; i++) {
        int idx = base + i;
        v[i] = (idx < N_PROD) ? cnt[idx] : 0;
        s += v[i];
    }
    int incl = s;
#pragma unroll
    for (int o = 1; o < 32; o <<= 1) {
        int t = __shfl_up_sync(0xffffffffu, incl, o);
        if (lane >= o) incl += t;
    }
    __shared__ int wsum[32];
    if (lane == 31) wsum[wid] = incl;
    __syncthreads();
    if (wid == 0) {
        int w = wsum[lane];
#pragma unroll
        for (int o = 1; o < 32; o <<= 1) {
            int t = __shfl_up_sync(0xffffffffu, w, o);
            if (lane >= o) w += t;
        }
        wsum[lane] = w;
    }
    __syncthreads();
    int run = incl - s + (wid > 0 ? wsum[wid - 1] : 0);
#pragma unroll
    for (int i = 0; i < 10; i++) {
        int idx = base + i;
        if (idx < N_PROD) { off[idx] = run; cur[idx] = run; run += v[i]; }
    }
    if (tid == 1023) off[N_PROD] = run;
}

// ------------------------- all 5 scatters in one launch (gridDim.y = 5) ---------------
__global__ void scatter_all(EdgePtrs ep) {
    int rel = blockIdx.y;
    const int* src = ep.src[rel];
    const int* dst = ep.dst[rel];
    int* cur = g_cursor[rel];
    int* srt = g_sorted[rel];
    for (int i = blockIdx.x * blockDim.x + threadIdx.x; i < ep.E; i += gridDim.x * blockDim.x) {
        int d = dst[i];
        int p = atomicAdd(&cur[d], 1);
        srt[p] = src[i];
    }
}

// ------------------------- all 5 aggregations in one launch (gridDim.y = 5) -----------
// one warp per dst row; lane owns 16B (float4) of the 512B feature row
__global__ void agg_all(const float* __restrict__ x) {
    int gw = (blockIdx.x * blockDim.x + threadIdx.x) >> 5;
    if (gw >= N_PROD) return;
    int lane = threadIdx.x & 31;
    int rel = blockIdx.y;
    const int* off = g_offsets[rel];
    const int* srt = g_sorted[rel];
    int o0 = off[gw], o1 = off[gw + 1];
    const float4* x4 = (const float4*)x;
    float4 a = make_float4(0.f, 0.f, 0.f, 0.f);

    if (rel >= 2) {
        // SAGE mean of raw features, unroll 4 for MLP
        int e = o0;
        for (; e + 3 < o1; e += 4) {
            int s0 = srt[e], s1 = srt[e + 1], s2 = srt[e + 2], s3 = srt[e + 3];
            float4 v0 = x4[s0 * 32 + lane];
            float4 v1 = x4[s1 * 32 + lane];
            float4 v2 = x4[s2 * 32 + lane];
            float4 v3 = x4[s3 * 32 + lane];
            a.x += (v0.x + v1.x) + (v2.x + v3.x);
            a.y += (v0.y + v1.y) + (v2.y + v3.y);
            a.z += (v0.z + v1.z) + (v2.z + v3.z);
            a.w += (v0.w + v1.w) + (v2.w + v3.w);
        }
        for (; e < o1; e++) {
            int s0 = srt[e];
            float4 v0 = x4[s0 * 32 + lane];
            a.x += v0.x; a.y += v0.y; a.z += v0.z; a.w += v0.w;
        }
        int c = o1 - o0; if (c < 1) c = 1;
        float inv = 1.0f / (float)c;
        a.x *= inv; a.y *= inv; a.z *= inv; a.w *= inv;
    } else if (rel == 0) {
        // GCN symmetric norm
        float dd = (float)(o1 - o0);
        int e = o0;
        for (; e + 1 < o1; e += 2) {
            int s0 = srt[e], s1 = srt[e + 1];
            float n0 = rsqrtf((float)g_deg_s[s0] * dd);
            float n1 = rsqrtf((float)g_deg_s[s1] * dd);
            float4 v0 = x4[s0 * 32 + lane];
            float4 v1 = x4[s1 * 32 + lane];
            a.x += n0 * v0.x + n1 * v1.x;
            a.y += n0 * v0.y + n1 * v1.y;
            a.z += n0 * v0.z + n1 * v1.z;
            a.w += n0 * v0.w + n1 * v1.w;
        }
        if (e < o1) {
            int s0 = srt[e];
            float n0 = rsqrtf((float)g_deg_s[s0] * dd);
            float4 v0 = x4[s0 * 32 + lane];
            a.x += n0 * v0.x; a.y += n0 * v0.y; a.z += n0 * v0.z; a.w += n0 * v0.w;
        }
    } else {
        // GAT edge-softmax
        if (o0 < o1) {
            float ldv = g_ld[gw];
            float m = -1e30f;
            for (int e = o0 + lane; e < o1; e += 32) {
                int s = srt[e];
                float l = g_ls[s] + ldv;
                l = (l > 0.f) ? l : 0.2f * l;
                m = fmaxf(m, l);
            }
#pragma unroll
            for (int o = 16; o; o >>= 1) m = fmaxf(m, __shfl_xor_sync(0xffffffffu, m, o));
            float den = 0.f;
            int e = o0;
            for (; e + 1 < o1; e += 2) {
                int s0 = srt[e], s1 = srt[e + 1];
                float l0 = g_ls[s0] + ldv;
                float l1 = g_ls[s1] + ldv;
                l0 = (l0 > 0.f) ? l0 : 0.2f * l0;
                l1 = (l1 > 0.f) ? l1 : 0.2f * l1;
                float w0 = __expf(l0 - m);
                float w1 = __expf(l1 - m);
                den += w0 + w1;
                float4 v0 = x4[s0 * 32 + lane];
                float4 v1 = x4[s1 * 32 + lane];
                a.x += w0 * v0.x + w1 * v1.x;
                a.y += w0 * v0.y + w1 * v1.y;
                a.z += w0 * v0.z + w1 * v1.z;
                a.w += w0 * v0.w + w1 * v1.w;
            }
            if (e < o1) {
                int s0 = srt[e];
                float l0 = g_ls[s0] + ldv;
                l0 = (l0 > 0.f) ? l0 : 0.2f * l0;
                float w0 = __expf(l0 - m);
                den += w0;
                float4 v0 = x4[s0 * 32 + lane];
                a.x += w0 * v0.x; a.y += w0 * v0.y; a.z += w0 * v0.z; a.w += w0 * v0.w;
            }
            float inv = 1.0f / den;
            a.x *= inv; a.y *= inv; a.z *= inv; a.w *= inv;
        }
    }
    ((float4*)g_feat[rel])[gw * 32 + lane] = a;
}

// ------------------------- fused GEMM: relu(sum_p S_p@W_p + bias) @ W_out + b_out ------
// Stage A: acc[64x128] over K=6*128, BM=64 BN=128 BK=16, 256 thr, 4x8 micro.
// Stage B: relu tile -> smem (aliased), multiply by W_out [128x64] -> out [64x64].
__global__ void gemm_fused(const float* __restrict__ xprod,
                           const float* __restrict__ Wg, const float* __restrict__ Wsg,
                           const float* __restrict__ Wlt, const float* __restrict__ Wlf,
                           const float* __restrict__ Wld,
                           const float* __restrict__ Wout, const float* __restrict__ bout,
                           float* __restrict__ out) {
    __shared__ __align__(16) char sbuf[37120];
    float (*As)[65] = (float (*)[65])sbuf;
    float (*Bs)[128] = (float (*)[128])(sbuf + 4160);
    int tid = threadIdx.x;
    int ty = tid >> 4, tx = tid & 15;
    int m0 = blockIdx.x * 64;
    float acc[4][8];
#pragma unroll
    for (int i = 0; i < 4; i++)
#pragma unroll
        for (int j = 0; j < 8; j++) acc[i][j] = 0.f;

    const float* Asrc[6] = {g_feat[0], g_feat[1], g_feat[2], g_feat[3], g_feat[4], xprod};
    const float* Bsrc[6] = {Wg, Wsg, Wlt, Wlf, Wld, g_wrsum};

    for (int p = 0; p < 6; p++) {
        const float* A = Asrc[p];
        const float* B = Bsrc[p];
        for (int kt = 0; kt < 8; kt++) {
            int kc0 = kt * 16;
#pragma unroll
            for (int j = 0; j < 4; j++) {
                int idx = tid + j * 256;
                int m = idx >> 4, kk = idx & 15;
                int row = m0 + m;
                As[kk][m] = (row < N_PROD) ? A[row * 128 + kc0 + kk] : 0.f;
            }
#pragma unroll
            for (int j = 0; j < 8; j++) {
                int idx = tid + j * 256;
                int kk = idx >> 7, n = idx & 127;
                Bs[kk][n] = B[(kc0 + kk) * 128 + n];
            }
            __syncthreads();
#pragma unroll
            for (int kk = 0; kk < 16; kk++) {
                float av[4], bv[8];
#pragma unroll
                for (int i = 0; i < 4; i++) av[i] = As[kk][ty * 4 + i];
#pragma unroll
                for (int j = 0; j < 8; j++) bv[j] = Bs[kk][tx * 8 + j];
#pragma unroll
                for (int i = 0; i < 4; i++)
#pragma unroll
                    for (int j = 0; j < 8; j++) acc[i][j] += av[i] * bv[j];
            }
            __syncthreads();
        }
    }

    // Stage B (smem aliased over stage-A buffers; stage A ended with a barrier)
    float (*Rs)[129] = (float (*)[129])sbuf;
    float (*Bs2)[64] = (float (*)[64])(sbuf + 33024);
#pragma unroll
    for (int i = 0; i < 4; i++) {
        int m = ty * 4 + i;
#pragma unroll
        for (int j = 0; j < 8; j++) {
            int c = tx * 8 + j;
            float v = acc[i][j] + g_bias[c];
            Rs[m][c] = (v > 0.f) ? v : 0.f;
        }
    }
    __syncthreads();

    float acc2[4][4];
#pragma unroll
    for (int i = 0; i < 4; i++)
#pragma unroll
        for (int j = 0; j < 4; j++) acc2[i][j] = 0.f;

    for (int kt = 0; kt < 8; kt++) {
#pragma unroll
        for (int j = 0; j < 4; j++) {
            int idx = tid + j * 256;
            int kk = idx >> 6, n = idx & 63;
            Bs2[kk][n] = Wout[(kt * 16 + kk) * 64 + n];
        }
        __syncthreads();
#pragma unroll
        for (int kk = 0; kk < 16; kk++) {
            float av[4], bv[4];
#pragma unroll
            for (int i = 0; i < 4; i++) av[i] = Rs[ty * 4 + i][kt * 16 + kk];
#pragma unroll
            for (int j = 0; j < 4; j++) bv[j] = Bs2[kk][tx * 4 + j];
#pragma unroll
            for (int i = 0; i < 4; i++)
#pragma unroll
                for (int j = 0; j < 4; j++) acc2[i][j] += av[i] * bv[j];
        }
        __syncthreads();
    }
#pragma unroll
    for (int i = 0; i < 4; i++) {
        int row = m0 + ty * 4 + i;
        if (row < N_PROD) {
#pragma unroll
            for (int j = 0; j < 4; j++) {
                int c = tx * 4 + j;
                out[row * 64 + c] = acc2[i][j] + bout[c];
            }
        }
    }
}

// ------------------------- launch -------------------------
extern "C" void kernel_launch(void* const* d_in, const int* in_sizes, int n_in,
                              void* d_out, int out_size) {
    const float* x_cust = (const float*)d_in[0];
    const float* x_prod = (const float*)d_in[1];
    EdgePtrs ep;
    for (int r = 0; r < NREL; r++) {
        ep.src[r] = (const int*)d_in[2 + 2 * r];
        ep.dst[r] = (const int*)d_in[3 + 2 * r];
    }
    ep.E = in_sizes[2];
    const float* W_gcn  = (const float*)d_in[12];
    const float* b_gcn  = (const float*)d_in[13];
    const float* Ws_gat = (const float*)d_in[14];
    const float* Wd_gat = (const float*)d_in[15];
    const float* a_s    = (const float*)d_in[16];
    const float* a_d    = (const float*)d_in[17];
    const float* b_gat  = (const float*)d_in[18];
    const float* Wl_to  = (const float*)d_in[19];
    const float* b_to   = (const float*)d_in[20];
    const float* Wr_to  = (const float*)d_in[21];
    const float* Wl_fr  = (const float*)d_in[22];
    const float* b_fr   = (const float*)d_in[23];
    const float* Wr_fr  = (const float*)d_in[24];
    const float* Wl_dv  = (const float*)d_in[25];
    const float* b_dv   = (const float*)d_in[26];
    const float* Wr_dv  = (const float*)d_in[27];
    const float* W_out  = (const float*)d_in[28];
    const float* b_out  = (const float*)d_in[29];

    setup_kernel<<<321, 256>>>(Ws_gat, Wd_gat, a_s, a_d,
                               b_gcn, b_gat, b_to, b_fr, b_dv,
                               Wr_to, Wr_fr, Wr_dv);
    rowdot_all<<<(N_CUST + N_PROD + 7) / 8, 256>>>(x_cust, x_prod);

    dim3 hgrid(256, 6);
    hist_all<<<hgrid, 256>>>(ep);
    scan_all<<<5, 1024>>>();
    dim3 sgrid(256, 5);
    scatter_all<<<sgrid, 256>>>(ep);

    dim3 agrid((N_PROD + 7) / 8, 5);
    agg_all<<<agrid, 256>>>(x_cust);

    gemm_fused<<<(N_PROD + 63) / 64, 256>>>(x_prod, W_gcn, Ws_gat, Wl_to, Wl_fr, Wl_dv,
                                            W_out, b_out, (float*)d_out);
}

// round 3
// speedup vs baseline: 1.7987x; 1.2943x over previous
#include <cuda_runtime.h>
#include <cuda_fp16.h>

#define N_CUST 100000
#define N_PROD 10000
#define NREL 5
#define EMAX 500000

// ------------------------- device scratch (no allocs allowed) -------------------------
__device__ float g_wsvec[128];            // Ws_gat @ a_s
__device__ float g_wdvec[128];            // Wd_gat @ a_d
__device__ float g_bias[128];             // sum of 5 branch biases
__device__ float g_wrsum[128 * 128];      // Wr_to + Wr_from + Wr_div
__device__ float g_ls[N_CUST];
__device__ float g_ld[N_PROD];
__device__ int   g_deg_s[N_CUST];         // purchase src degree
__device__ int   g_counts[NREL][N_PROD];
__device__ int   g_offsets[NREL][N_PROD + 1];
__device__ int   g_cursor[NREL][N_PROD];
__device__ int   g_part[NREL][32];
__device__ int   g_sorted[NREL][EMAX];
__device__ uint2 g_xch[N_CUST * 32];      // x_cust as fp16, 32 x uint2 (8 halves... 4 halves ea) per row
__device__ float g_feat[NREL][N_PROD * 128];

struct EdgePtrs {
    const int* src[NREL];
    const int* dst[NREL];
    int E;
};

// ------------------------- f32x2 helpers -------------------------
__device__ __forceinline__ unsigned long long pack2(float lo, float hi) {
    unsigned long long r;
    asm("mov.b64 %0, {%1, %2};" : "=l"(r) : "f"(lo), "f"(hi));
    return r;
}
__device__ __forceinline__ void unpack2(unsigned long long v, float& lo, float& hi) {
    asm("mov.b64 {%0, %1}, %2;" : "=f"(lo), "=f"(hi) : "l"(v));
}
__device__ __forceinline__ void ffma2(unsigned long long& d, unsigned long long a,
                                      unsigned long long b) {
    asm("fma.rn.f32x2 %0, %1, %2, %0;" : "+l"(d) : "l"(a), "l"(b));
}

// ------------------------- setup: zero counters + weight prep, one launch -------------
__global__ void setup_kernel(const float* __restrict__ Ws, const float* __restrict__ Wd,
                             const float* __restrict__ a_s, const float* __restrict__ a_d,
                             const float* __restrict__ bg, const float* __restrict__ bgat,
                             const float* __restrict__ bto, const float* __restrict__ bfrom,
                             const float* __restrict__ bdiv,
                             const float* __restrict__ Wrt, const float* __restrict__ Wrf,
                             const float* __restrict__ Wrd) {
    int b = blockIdx.x;
    if (b == 0) {
        int t = threadIdx.x;
        if (t < 128) {
            float s1 = 0.f, s2 = 0.f;
            for (int j = 0; j < 128; j++) {
                s1 += Ws[t * 128 + j] * a_s[j];
                s2 += Wd[t * 128 + j] * a_d[j];
            }
            g_wsvec[t] = s1;
            g_wdvec[t] = s2;
            g_bias[t] = bg[t] + bgat[t] + bto[t] + bfrom[t] + bdiv[t];
        }
    } else if (b <= 64) {
        int i = (b - 1) * 256 + threadIdx.x;
        g_wrsum[i] = Wrt[i] + Wrf[i] + Wrd[i];
    } else {
        int n = N_CUST + NREL * N_PROD;
        int stride = (gridDim.x - 65) * 256;
        for (int i = (b - 65) * 256 + threadIdx.x; i < n; i += stride) {
            if (i < N_CUST) g_deg_s[i] = 0;
            else ((int*)g_counts)[i - N_CUST] = 0;
        }
    }
}

// ------------------------- ls/ld + fp16 conversion of x_cust, one launch --------------
__global__ void rowdot_conv(const float* __restrict__ xc, const float* __restrict__ xp) {
    int gw = (blockIdx.x * blockDim.x + threadIdx.x) >> 5;
    int lane = threadIdx.x & 31;
    if (gw >= N_CUST + N_PROD) return;
    float4 wv, xv;
    if (gw < N_CUST) {
        wv = ((const float4*)g_wsvec)[lane];
        xv = ((const float4*)xc)[gw * 32 + lane];
        __half2 h0 = __floats2half2_rn(xv.x, xv.y);
        __half2 h1 = __floats2half2_rn(xv.z, xv.w);
        uint2 u;
        u.x = *reinterpret_cast<unsigned*>(&h0);
        u.y = *reinterpret_cast<unsigned*>(&h1);
        g_xch[gw * 32 + lane] = u;
    } else {
        wv = ((const float4*)g_wdvec)[lane];
        xv = ((const float4*)xp)[(gw - N_CUST) * 32 + lane];
    }
    float d = xv.x * wv.x + xv.y * wv.y + xv.z * wv.z + xv.w * wv.w;
#pragma unroll
    for (int o = 16; o; o >>= 1) d += __shfl_xor_sync(0xffffffffu, d, o);
    if (lane == 0) {
        if (gw < N_CUST) g_ls[gw] = d; else g_ld[gw - N_CUST] = d;
    }
}

// ------------------------- all 6 histograms in one launch (gridDim.y = 6) -------------
__global__ void hist_all(EdgePtrs ep) {
    int y = blockIdx.y;
    const int* idx;
    int* bins;
    if (y == 0) { idx = ep.src[0]; bins = g_deg_s; }
    else        { idx = ep.dst[y - 1]; bins = g_counts[y - 1]; }
    for (int i = blockIdx.x * blockDim.x + threadIdx.x; i < ep.E; i += gridDim.x * blockDim.x)
        atomicAdd(&bins[idx[i]], 1);
}

// ------------------------- two-phase scan: grid (32, 5) ------------------------------
__global__ void scan_p1() {
    int rel = blockIdx.y;
    int bx = blockIdx.x;
    int tid = threadIdx.x;  // 320 threads
    int i = bx * 320 + tid;
    int v = (i < N_PROD) ? g_counts[rel][i] : 0;
#pragma unroll
    for (int o = 16; o; o >>= 1) v += __shfl_xor_sync(0xffffffffu, v, o);
    __shared__ int wsum[10];
    if ((tid & 31) == 0) wsum[tid >> 5] = v;
    __syncthreads();
    if (tid == 0) {
        int s = 0;
#pragma unroll
        for (int w = 0; w < 10; w++) s += wsum[w];
        g_part[rel][bx] = s;
    }
}

__global__ void scan_p2() {
    int rel = blockIdx.y;
    int bx = blockIdx.x;
    int tid = threadIdx.x;  // 320 threads
    int lane = tid & 31, wid = tid >> 5;
    __shared__ int wsum[10];
    __shared__ int spart[32];
    int i = bx * 320 + tid;
    int v = (i < N_PROD) ? g_counts[rel][i] : 0;
    int incl = v;
#pragma unroll
    for (int o = 1; o < 32; o <<= 1) {
        int t = __shfl_up_sync(0xffffffffu, incl, o);
        if (lane >= o) incl += t;
    }
    if (lane == 31) wsum[wid] = incl;
    __syncthreads();
    if (tid < 32) {
        // inclusive scan of the 32 block partials
        int p = g_part[rel][tid];
#pragma unroll
        for (int o = 1; o < 32; o <<= 1) {
            int t = __shfl_up_sync(0xffffffffu, p, o);
            if (tid >= o) p += t;
        }
        spart[tid] = p;
        // scan the 10 warp sums (serial by lane 0, tiny)
        if (tid == 0) {
            int run = 0;
#pragma unroll
            for (int w = 0; w < 10; w++) { int t = wsum[w]; wsum[w] = run; run += t; }
        }
    }
    __syncthreads();
    int blockoff = (bx > 0) ? spart[bx - 1] : 0;
    int excl = blockoff + wsum[wid] + incl - v;
    if (i < N_PROD) {
        g_offsets[rel][i] = excl;
        g_cursor[rel][i] = excl;
    }
    if (bx == 31 && tid == 319) g_offsets[rel][N_PROD] = spart[31];
}

// ------------------------- all 5 scatters in one launch (gridDim.y = 5) ---------------
__global__ void scatter_all(EdgePtrs ep) {
    int rel = blockIdx.y;
    const int* src = ep.src[rel];
    const int* dst = ep.dst[rel];
    int* cur = g_cursor[rel];
    int* srt = g_sorted[rel];
    for (int i = blockIdx.x * blockDim.x + threadIdx.x; i < ep.E; i += gridDim.x * blockDim.x) {
        int d = dst[i];
        int p = atomicAdd(&cur[d], 1);
        srt[p] = src[i];
    }
}

// ------------------------- fp16 gather helper -------------------------
__device__ __forceinline__ void acc_h(float4& a, uint2 u, float w) {
    __half2 h0 = *reinterpret_cast<__half2*>(&u.x);
    __half2 h1 = *reinterpret_cast<__half2*>(&u.y);
    float2 f0 = __half22float2(h0);
    float2 f1 = __half22float2(h1);
    a.x += w * f0.x; a.y += w * f0.y; a.z += w * f1.x; a.w += w * f1.y;
}

// ------------------------- all 5 aggregations in one launch (gridDim.y = 5) -----------
__global__ void agg_all() {
    int gw = (blockIdx.x * blockDim.x + threadIdx.x) >> 5;
    if (gw >= N_PROD) return;
    int lane = threadIdx.x & 31;
    int rel = blockIdx.y;
    const int* off = g_offsets[rel];
    const int* srt = g_sorted[rel];
    int o0 = off[gw], o1 = off[gw + 1];
    const uint2* xh = g_xch;
    float4 a = make_float4(0.f, 0.f, 0.f, 0.f);

    if (rel >= 2) {
        // SAGE mean, unroll 4 for MLP
        int e = o0;
        for (; e + 3 < o1; e += 4) {
            int s0 = srt[e], s1 = srt[e + 1], s2 = srt[e + 2], s3 = srt[e + 3];
            uint2 u0 = xh[s0 * 32 + lane];
            uint2 u1 = xh[s1 * 32 + lane];
            uint2 u2 = xh[s2 * 32 + lane];
            uint2 u3 = xh[s3 * 32 + lane];
            acc_h(a, u0, 1.f); acc_h(a, u1, 1.f); acc_h(a, u2, 1.f); acc_h(a, u3, 1.f);
        }
        for (; e < o1; e++) {
            uint2 u0 = xh[srt[e] * 32 + lane];
            acc_h(a, u0, 1.f);
        }
        int c = o1 - o0; if (c < 1) c = 1;
        float inv = 1.0f / (float)c;
        a.x *= inv; a.y *= inv; a.z *= inv; a.w *= inv;
    } else if (rel == 0) {
        // GCN symmetric norm
        float dd = (float)(o1 - o0);
        int e = o0;
        for (; e + 1 < o1; e += 2) {
            int s0 = srt[e], s1 = srt[e + 1];
            float n0 = rsqrtf((float)g_deg_s[s0] * dd);
            float n1 = rsqrtf((float)g_deg_s[s1] * dd);
            uint2 u0 = xh[s0 * 32 + lane];
            uint2 u1 = xh[s1 * 32 + lane];
            acc_h(a, u0, n0); acc_h(a, u1, n1);
        }
        if (e < o1) {
            int s0 = srt[e];
            float n0 = rsqrtf((float)g_deg_s[s0] * dd);
            uint2 u0 = xh[s0 * 32 + lane];
            acc_h(a, u0, n0);
        }
    } else {
        // GAT edge-softmax
        if (o0 < o1) {
            float ldv = g_ld[gw];
            float m = -1e30f;
            for (int e = o0 + lane; e < o1; e += 32) {
                float l = g_ls[srt[e]] + ldv;
                l = (l > 0.f) ? l : 0.2f * l;
                m = fmaxf(m, l);
            }
#pragma unroll
            for (int o = 16; o; o >>= 1) m = fmaxf(m, __shfl_xor_sync(0xffffffffu, m, o));
            float den = 0.f;
            int e = o0;
            for (; e + 1 < o1; e += 2) {
                int s0 = srt[e], s1 = srt[e + 1];
                float l0 = g_ls[s0] + ldv;
                float l1 = g_ls[s1] + ldv;
                l0 = (l0 > 0.f) ? l0 : 0.2f * l0;
                l1 = (l1 > 0.f) ? l1 : 0.2f * l1;
                float w0 = __expf(l0 - m);
                float w1 = __expf(l1 - m);
                den += w0 + w1;
                uint2 u0 = xh[s0 * 32 + lane];
                uint2 u1 = xh[s1 * 32 + lane];
                acc_h(a, u0, w0); acc_h(a, u1, w1);
            }
            if (e < o1) {
                int s0 = srt[e];
                float l0 = g_ls[s0] + ldv;
                l0 = (l0 > 0.f) ? l0 : 0.2f * l0;
                float w0 = __expf(l0 - m);
                den += w0;
                uint2 u0 = xh[s0 * 32 + lane];
                acc_h(a, u0, w0);
            }
            float inv = 1.0f / den;
            a.x *= inv; a.y *= inv; a.z *= inv; a.w *= inv;
        }
    }
    ((float4*)g_feat[rel])[gw * 32 + lane] = a;
}

// ------------------------- fused GEMM with f32x2 packed FMA ---------------------------
// Stage A: acc[64x128] over K=6*128, BM=64 BN=128 BK=32, 256 thr, 4x8 micro (f32x2).
// Stage B: relu tile -> smem (aliased), multiply by W_out [128x64] -> out [64x64].
__global__ void gemm_fused(const float* __restrict__ xprod,
                           const float* __restrict__ Wg, const float* __restrict__ Wsg,
                           const float* __restrict__ Wlt, const float* __restrict__ Wlf,
                           const float* __restrict__ Wld,
                           const float* __restrict__ Wout, const float* __restrict__ bout,
                           float* __restrict__ out) {
    __shared__ __align__(16) char sbuf[37120];
    float (*As)[65] = (float (*)[65])sbuf;               // 32x65 = 8320 B
    float (*Bs)[128] = (float (*)[128])(sbuf + 8320);    // 32x128 = 16384 B
    int tid = threadIdx.x;
    int ty = tid >> 4, tx = tid & 15;
    int m0 = blockIdx.x * 64;
    unsigned long long acc[4][4];
#pragma unroll
    for (int i = 0; i < 4; i++)
#pragma unroll
        for (int j = 0; j < 4; j++) acc[i][j] = 0ull;

    const float* Asrc[6] = {g_feat[0], g_feat[1], g_feat[2], g_feat[3], g_feat[4], xprod};
    const float* Bsrc[6] = {Wg, Wsg, Wlt, Wlf, Wld, g_wrsum};

    for (int p = 0; p < 6; p++) {
        const float* A = Asrc[p];
        const float* B = Bsrc[p];
        for (int kt = 0; kt < 4; kt++) {
            int kc0 = kt * 32;
            // load A tile: 64x32 floats = 512 float4, 2 per thread
#pragma unroll
            for (int t = 0; t < 2; t++) {
                int fidx = tid + t * 256;
                int m = fidx >> 3, kq = fidx & 7;
                int row = m0 + m;
                float4 v = make_float4(0.f, 0.f, 0.f, 0.f);
                if (row < N_PROD) v = *(const float4*)&A[row * 128 + kc0 + kq * 4];
                As[kq * 4 + 0][m] = v.x;
                As[kq * 4 + 1][m] = v.y;
                As[kq * 4 + 2][m] = v.z;
                As[kq * 4 + 3][m] = v.w;
            }
            // load B tile: 32x128 floats = 1024 float4, 4 per thread
#pragma unroll
            for (int t = 0; t < 4; t++) {
                int fidx = tid + t * 256;
                int kk = fidx >> 5, nq = fidx & 31;
                *(float4*)&Bs[kk][nq * 4] = *(const float4*)&B[(kc0 + kk) * 128 + nq * 4];
            }
            __syncthreads();
#pragma unroll
            for (int kk = 0; kk < 32; kk++) {
                unsigned long long av2[4], bv2[4];
#pragma unroll
                for (int i = 0; i < 4; i++) {
                    float av = As[kk][ty * 4 + i];
                    av2[i] = pack2(av, av);
                }
#pragma unroll
                for (int j = 0; j < 4; j++) {
                    float2 b2 = *(const float2*)&Bs[kk][tx * 8 + j * 2];
                    bv2[j] = pack2(b2.x, b2.y);
                }
#pragma unroll
                for (int i = 0; i < 4; i++)
#pragma unroll
                    for (int j = 0; j < 4; j++) ffma2(acc[i][j], av2[i], bv2[j]);
            }
            __syncthreads();
        }
    }

    // Stage B (smem aliased; stage A ended with a barrier)
    float (*Rs)[129] = (float (*)[129])sbuf;             // 64x129 = 33024 B
    float (*Bs2)[64] = (float (*)[64])(sbuf + 33024);    // 16x64 = 4096 B
#pragma unroll
    for (int i = 0; i < 4; i++) {
        int m = ty * 4 + i;
#pragma unroll
        for (int j = 0; j < 4; j++) {
            int c = tx * 8 + j * 2;
            float lo, hi;
            unpack2(acc[i][j], lo, hi);
            float v0 = lo + g_bias[c];
            float v1 = hi + g_bias[c + 1];
            Rs[m][c] = (v0 > 0.f) ? v0 : 0.f;
            Rs[m][c + 1] = (v1 > 0.f) ? v1 : 0.f;
        }
    }
    __syncthreads();

    float acc2[4][4];
#pragma unroll
    for (int i = 0; i < 4; i++)
#pragma unroll
        for (int j = 0; j < 4; j++) acc2[i][j] = 0.f;

    for (int kt = 0; kt < 8; kt++) {
#pragma unroll
        for (int t = 0; t < 4; t++) {
            int idx = tid + t * 256;
            int kk = idx >> 6, n = idx & 63;
            Bs2[kk][n] = Wout[(kt * 16 + kk) * 64 + n];
        }
        __syncthreads();
#pragma unroll
        for (int kk = 0; kk < 16; kk++) {
            float av[4], bv[4];
#pragma unroll
            for (int i = 0; i < 4; i++) av[i] = Rs[ty * 4 + i][kt * 16 + kk];
#pragma unroll
            for (int j = 0; j < 4; j++) bv[j] = Bs2[kk][tx * 4 + j];
#pragma unroll
            for (int i = 0; i < 4; i++)
#pragma unroll
                for (int j = 0; j < 4; j++) acc2[i][j] += av[i] * bv[j];
        }
        __syncthreads();
    }
#pragma unroll
    for (int i = 0; i < 4; i++) {
        int row = m0 + ty * 4 + i;
        if (row < N_PROD) {
#pragma unroll
            for (int j = 0; j < 4; j++) {
                int c = tx * 4 + j;
                out[row * 64 + c] = acc2[i][j] + bout[c];
            }
        }
    }
}

// ------------------------- launch -------------------------
extern "C" void kernel_launch(void* const* d_in, const int* in_sizes, int n_in,
                              void* d_out, int out_size) {
    const float* x_cust = (const float*)d_in[0];
    const float* x_prod = (const float*)d_in[1];
    EdgePtrs ep;
    for (int r = 0; r < NREL; r++) {
        ep.src[r] = (const int*)d_in[2 + 2 * r];
        ep.dst[r] = (const int*)d_in[3 + 2 * r];
    }
    ep.E = in_sizes[2];
    const float* W_gcn  = (const float*)d_in[12];
    const float* b_gcn  = (const float*)d_in[13];
    const float* Ws_gat = (const float*)d_in[14];
    const float* Wd_gat = (const float*)d_in[15];
    const float* a_s    = (const float*)d_in[16];
    const float* a_d    = (const float*)d_in[17];
    const float* b_gat  = (const float*)d_in[18];
    const float* Wl_to  = (const float*)d_in[19];
    const float* b_to   = (const float*)d_in[20];
    const float* Wr_to  = (const float*)d_in[21];
    const float* Wl_fr  = (const float*)d_in[22];
    const float* b_fr   = (const float*)d_in[23];
    const float* Wr_fr  = (const float*)d_in[24];
    const float* Wl_dv  = (const float*)d_in[25];
    const float* b_dv   = (const float*)d_in[26];
    const float* Wr_dv  = (const float*)d_in[27];
    const float* W_out  = (const float*)d_in[28];
    const float* b_out  = (const float*)d_in[29];

    setup_kernel<<<321, 256>>>(Ws_gat, Wd_gat, a_s, a_d,
                               b_gcn, b_gat, b_to, b_fr, b_dv,
                               Wr_to, Wr_fr, Wr_dv);
    rowdot_conv<<<(N_CUST + N_PROD + 7) / 8, 256>>>(x_cust, x_prod);

    dim3 hgrid(256, 6);
    hist_all<<<hgrid, 256>>>(ep);
    dim3 sgrid32(32, 5);
    scan_p1<<<sgrid32, 320>>>();
    scan_p2<<<sgrid32, 320>>>();
    dim3 sgrid(256, 5);
    scatter_all<<<sgrid, 256>>>(ep);

    dim3 agrid((N_PROD + 7) / 8, 5);
    agg_all<<<agrid, 256>>>();

    gemm_fused<<<(N_PROD + 63) / 64, 256>>>(x_prod, W_gcn, Ws_gat, Wl_to, Wl_fr, Wl_dv,
                                            W_out, b_out, (float*)d_out);
}

// round 4
// speedup vs baseline: 1.8165x; 1.0099x over previous
#include <cuda_runtime.h>
#include <cuda_fp16.h>

#define N_CUST 100000
#define N_PROD 10000
#define NREL 5
#define EMAX 500000
#define ROWDOT_BLOCKS 13750   // (N_CUST+N_PROD) warps / 8

// ------------------------- device scratch (no allocs allowed) -------------------------
__device__ float g_wsvec[128];            // Ws_gat @ a_s
__device__ float g_wdvec[128];            // Wd_gat @ a_d
__device__ float g_bias[128];             // sum of 5 branch biases
__device__ float g_wrsum[128 * 128];      // Wr_to + Wr_from + Wr_div
__device__ float g_ls[N_CUST];
__device__ float g_ld[N_PROD];
__device__ int   g_deg_s[N_CUST];         // purchase src degree
__device__ int   g_counts[NREL][N_PROD];
__device__ int   g_offsets[NREL][N_PROD + 1];
__device__ int   g_cursor[NREL][N_PROD];
__device__ int   g_part[NREL][32];
__device__ int   g_sorted[NREL][EMAX];
__device__ uint2 g_xch[N_CUST * 32];      // x_cust rows as fp16 (32 x 8B per row)
__device__ float g_feat[NREL][N_PROD * 128];

struct EdgePtrs {
    const int* src[NREL];
    const int* dst[NREL];
    int E;
};

// ------------------------- f32x2 helpers -------------------------
__device__ __forceinline__ unsigned long long pack2(float lo, float hi) {
    unsigned long long r;
    asm("mov.b64 %0, {%1, %2};" : "=l"(r) : "f"(lo), "f"(hi));
    return r;
}
__device__ __forceinline__ void unpack2(unsigned long long v, float& lo, float& hi) {
    asm("mov.b64 {%0, %1}, %2;" : "=f"(lo), "=f"(hi) : "l"(v));
}
__device__ __forceinline__ void ffma2(unsigned long long& d, unsigned long long a,
                                      unsigned long long b) {
    asm("fma.rn.f32x2 %0, %1, %2, %0;" : "+l"(d) : "l"(a), "l"(b));
}

// ------------------------- setup: zero counters + weight prep -------------------------
__global__ void setup_kernel(const float* __restrict__ Ws, const float* __restrict__ Wd,
                             const float* __restrict__ a_s, const float* __restrict__ a_d,
                             const float* __restrict__ bg, const float* __restrict__ bgat,
                             const float* __restrict__ bto, const float* __restrict__ bfrom,
                             const float* __restrict__ bdiv,
                             const float* __restrict__ Wrt, const float* __restrict__ Wrf,
                             const float* __restrict__ Wrd) {
    int b = blockIdx.x;
    if (b == 0) {
        int t = threadIdx.x;
        if (t < 128) {
            float s1 = 0.f, s2 = 0.f;
            for (int j = 0; j < 128; j++) {
                s1 += Ws[t * 128 + j] * a_s[j];
                s2 += Wd[t * 128 + j] * a_d[j];
            }
            g_wsvec[t] = s1;
            g_wdvec[t] = s2;
            g_bias[t] = bg[t] + bgat[t] + bto[t] + bfrom[t] + bdiv[t];
        }
    } else if (b <= 64) {
        int i = (b - 1) * 256 + threadIdx.x;
        g_wrsum[i] = Wrt[i] + Wrf[i] + Wrd[i];
    } else {
        int n = N_CUST + NREL * N_PROD;
        int stride = (gridDim.x - 65) * 256;
        for (int i = (b - 65) * 256 + threadIdx.x; i < n; i += stride) {
            if (i < N_CUST) g_deg_s[i] = 0;
            else ((int*)g_counts)[i - N_CUST] = 0;
        }
    }
}

// -------------- phase1: rowdot+fp16 convert (blocks < ROWDOT_BLOCKS) + hist ------------
__global__ void phase1_kernel(const float* __restrict__ xc, const float* __restrict__ xp,
                              EdgePtrs ep) {
    int b = blockIdx.x;
    if (b < ROWDOT_BLOCKS) {
        int gw = (b * 256 + (int)threadIdx.x) >> 5;
        int lane = threadIdx.x & 31;
        float4 wv, xv;
        if (gw < N_CUST) {
            wv = ((const float4*)g_wsvec)[lane];
            xv = ((const float4*)xc)[gw * 32 + lane];
            __half2 h0 = __floats2half2_rn(xv.x, xv.y);
            __half2 h1 = __floats2half2_rn(xv.z, xv.w);
            uint2 u;
            u.x = *reinterpret_cast<unsigned*>(&h0);
            u.y = *reinterpret_cast<unsigned*>(&h1);
            g_xch[gw * 32 + lane] = u;
        } else {
            wv = ((const float4*)g_wdvec)[lane];
            xv = ((const float4*)xp)[(gw - N_CUST) * 32 + lane];
        }
        float d = xv.x * wv.x + xv.y * wv.y + xv.z * wv.z + xv.w * wv.w;
#pragma unroll
        for (int o = 16; o; o >>= 1) d += __shfl_xor_sync(0xffffffffu, d, o);
        if (lane == 0) {
            if (gw < N_CUST) g_ls[gw] = d; else g_ld[gw - N_CUST] = d;
        }
    } else {
        int j = b - ROWDOT_BLOCKS;          // 0 .. 6*256-1
        int y = j >> 8;                     // relation slot 0..5
        int bx = j & 255;
        const int* idx;
        int* bins;
        if (y == 0) { idx = ep.src[0]; bins = g_deg_s; }
        else        { idx = ep.dst[y - 1]; bins = g_counts[y - 1]; }
        for (int i = bx * 256 + (int)threadIdx.x; i < ep.E; i += 256 * 256)
            atomicAdd(&bins[idx[i]], 1);
    }
}

// ------------------------- two-phase scan: grid (32, 5) ------------------------------
__global__ void scan_p1() {
    int rel = blockIdx.y;
    int bx = blockIdx.x;
    int tid = threadIdx.x;  // 320 threads
    int i = bx * 320 + tid;
    int v = (i < N_PROD) ? g_counts[rel][i] : 0;
#pragma unroll
    for (int o = 16; o; o >>= 1) v += __shfl_xor_sync(0xffffffffu, v, o);
    __shared__ int wsum[10];
    if ((tid & 31) == 0) wsum[tid >> 5] = v;
    __syncthreads();
    if (tid == 0) {
        int s = 0;
#pragma unroll
        for (int w = 0; w < 10; w++) s += wsum[w];
        g_part[rel][bx] = s;
    }
}

__global__ void scan_p2() {
    int rel = blockIdx.y;
    int bx = blockIdx.x;
    int tid = threadIdx.x;  // 320 threads
    int lane = tid & 31, wid = tid >> 5;
    __shared__ int wsum[10];
    __shared__ int spart[32];
    int i = bx * 320 + tid;
    int v = (i < N_PROD) ? g_counts[rel][i] : 0;
    int incl = v;
#pragma unroll
    for (int o = 1; o < 32; o <<= 1) {
        int t = __shfl_up_sync(0xffffffffu, incl, o);
        if (lane >= o) incl += t;
    }
    if (lane == 31) wsum[wid] = incl;
    __syncthreads();
    if (tid < 32) {
        int p = g_part[rel][tid];
#pragma unroll
        for (int o = 1; o < 32; o <<= 1) {
            int t = __shfl_up_sync(0xffffffffu, p, o);
            if (tid >= o) p += t;
        }
        spart[tid] = p;
        if (tid == 0) {
            int run = 0;
#pragma unroll
            for (int w = 0; w < 10; w++) { int t = wsum[w]; wsum[w] = run; run += t; }
        }
    }
    __syncthreads();
    int blockoff = (bx > 0) ? spart[bx - 1] : 0;
    int excl = blockoff + wsum[wid] + incl - v;
    if (i < N_PROD) {
        g_offsets[rel][i] = excl;
        g_cursor[rel][i] = excl;
    }
    if (bx == 31 && tid == 319) g_offsets[rel][N_PROD] = spart[31];
}

// ------------------------- all 5 scatters in one launch (gridDim.y = 5) ---------------
__global__ void scatter_all(EdgePtrs ep) {
    int rel = blockIdx.y;
    const int* src = ep.src[rel];
    const int* dst = ep.dst[rel];
    int* cur = g_cursor[rel];
    int* srt = g_sorted[rel];
    for (int i = blockIdx.x * blockDim.x + threadIdx.x; i < ep.E; i += gridDim.x * blockDim.x) {
        int d = dst[i];
        int p = atomicAdd(&cur[d], 1);
        srt[p] = src[i];
    }
}

// ------------------------- fp16 gather helper -------------------------
__device__ __forceinline__ void acc_h(float4& a, uint2 u, float w) {
    __half2 h0 = *reinterpret_cast<__half2*>(&u.x);
    __half2 h1 = *reinterpret_cast<__half2*>(&u.y);
    float2 f0 = __half22float2(h0);
    float2 f1 = __half22float2(h1);
    a.x += w * f0.x; a.y += w * f0.y; a.z += w * f1.x; a.w += w * f1.y;
}

// ------------------------- all 5 aggregations in one launch (gridDim.y = 5) -----------
__global__ void agg_all() {
    int gw = (blockIdx.x * blockDim.x + threadIdx.x) >> 5;
    if (gw >= N_PROD) return;
    int lane = threadIdx.x & 31;
    int rel = blockIdx.y;
    const int* off = g_offsets[rel];
    const int* srt = g_sorted[rel];
    int o0 = off[gw], o1 = off[gw + 1];
    const uint2* xh = g_xch;
    float4 a = make_float4(0.f, 0.f, 0.f, 0.f);

    if (rel >= 2) {
        // SAGE mean, unroll 4
        int e = o0;
        for (; e + 3 < o1; e += 4) {
            int s0 = srt[e], s1 = srt[e + 1], s2 = srt[e + 2], s3 = srt[e + 3];
            uint2 u0 = xh[s0 * 32 + lane];
            uint2 u1 = xh[s1 * 32 + lane];
            uint2 u2 = xh[s2 * 32 + lane];
            uint2 u3 = xh[s3 * 32 + lane];
            acc_h(a, u0, 1.f); acc_h(a, u1, 1.f); acc_h(a, u2, 1.f); acc_h(a, u3, 1.f);
        }
        for (; e < o1; e++) {
            uint2 u0 = xh[srt[e] * 32 + lane];
            acc_h(a, u0, 1.f);
        }
        int c = o1 - o0; if (c < 1) c = 1;
        float inv = 1.0f / (float)c;
        a.x *= inv; a.y *= inv; a.z *= inv; a.w *= inv;
    } else if (rel == 0) {
        // GCN symmetric norm, unroll 4
        float dd = (float)(o1 - o0);
        int e = o0;
        for (; e + 3 < o1; e += 4) {
            int s0 = srt[e], s1 = srt[e + 1], s2 = srt[e + 2], s3 = srt[e + 3];
            float n0 = rsqrtf((float)g_deg_s[s0] * dd);
            float n1 = rsqrtf((float)g_deg_s[s1] * dd);
            float n2 = rsqrtf((float)g_deg_s[s2] * dd);
            float n3 = rsqrtf((float)g_deg_s[s3] * dd);
            uint2 u0 = xh[s0 * 32 + lane];
            uint2 u1 = xh[s1 * 32 + lane];
            uint2 u2 = xh[s2 * 32 + lane];
            uint2 u3 = xh[s3 * 32 + lane];
            acc_h(a, u0, n0); acc_h(a, u1, n1); acc_h(a, u2, n2); acc_h(a, u3, n3);
        }
        for (; e < o1; e++) {
            int s0 = srt[e];
            float n0 = rsqrtf((float)g_deg_s[s0] * dd);
            uint2 u0 = xh[s0 * 32 + lane];
            acc_h(a, u0, n0);
        }
    } else {
        // GAT edge-softmax — single pass, no max subtraction (logits bounded ~|3|,
        // softmax is shift-invariant so this is algebraically identical)
        if (o0 < o1) {
            float ldv = g_ld[gw];
            float den = 0.f;
            int e = o0;
            for (; e + 3 < o1; e += 4) {
                int s0 = srt[e], s1 = srt[e + 1], s2 = srt[e + 2], s3 = srt[e + 3];
                float l0 = g_ls[s0] + ldv;
                float l1 = g_ls[s1] + ldv;
                float l2 = g_ls[s2] + ldv;
                float l3 = g_ls[s3] + ldv;
                l0 = (l0 > 0.f) ? l0 : 0.2f * l0;
                l1 = (l1 > 0.f) ? l1 : 0.2f * l1;
                l2 = (l2 > 0.f) ? l2 : 0.2f * l2;
                l3 = (l3 > 0.f) ? l3 : 0.2f * l3;
                float w0 = __expf(l0);
                float w1 = __expf(l1);
                float w2 = __expf(l2);
                float w3 = __expf(l3);
                den += (w0 + w1) + (w2 + w3);
                uint2 u0 = xh[s0 * 32 + lane];
                uint2 u1 = xh[s1 * 32 + lane];
                uint2 u2 = xh[s2 * 32 + lane];
                uint2 u3 = xh[s3 * 32 + lane];
                acc_h(a, u0, w0); acc_h(a, u1, w1); acc_h(a, u2, w2); acc_h(a, u3, w3);
            }
            for (; e < o1; e++) {
                int s0 = srt[e];
                float l0 = g_ls[s0] + ldv;
                l0 = (l0 > 0.f) ? l0 : 0.2f * l0;
                float w0 = __expf(l0);
                den += w0;
                uint2 u0 = xh[s0 * 32 + lane];
                acc_h(a, u0, w0);
            }
            float inv = 1.0f / den;
            a.x *= inv; a.y *= inv; a.z *= inv; a.w *= inv;
        }
    }
    ((float4*)g_feat[rel])[gw * 32 + lane] = a;
}

// ------------------------- fused GEMM with f32x2 packed FMA ---------------------------
// Stage A: acc[64x128] over K=6*128, BM=64 BN=128 BK=32, 256 thr, 4x8 micro (f32x2),
//          vectorized LDS (As padded to 68 for 16B-aligned float4 rows).
// Stage B: relu tile -> smem (aliased), multiply by W_out [128x64] -> out [64x64].
__global__ void gemm_fused(const float* __restrict__ xprod,
                           const float* __restrict__ Wg, const float* __restrict__ Wsg,
                           const float* __restrict__ Wlt, const float* __restrict__ Wlf,
                           const float* __restrict__ Wld,
                           const float* __restrict__ Wout, const float* __restrict__ bout,
                           float* __restrict__ out) {
    __shared__ __align__(16) char sbuf[37120];
    float (*As)[68] = (float (*)[68])sbuf;               // 32x68x4 = 8704 B
    float (*Bs)[128] = (float (*)[128])(sbuf + 8704);    // 32x128x4 = 16384 B
    int tid = threadIdx.x;
    int ty = tid >> 4, tx = tid & 15;
    int m0 = blockIdx.x * 64;
    unsigned long long acc[4][4];
#pragma unroll
    for (int i = 0; i < 4; i++)
#pragma unroll
        for (int j = 0; j < 4; j++) acc[i][j] = 0ull;

    const float* Asrc[6] = {g_feat[0], g_feat[1], g_feat[2], g_feat[3], g_feat[4], xprod};
    const float* Bsrc[6] = {Wg, Wsg, Wlt, Wlf, Wld, g_wrsum};

    for (int p = 0; p < 6; p++) {
        const float* A = Asrc[p];
        const float* B = Bsrc[p];
        for (int kt = 0; kt < 4; kt++) {
            int kc0 = kt * 32;
            // load A tile: 64x32 floats = 512 float4, 2 per thread
#pragma unroll
            for (int t = 0; t < 2; t++) {
                int fidx = tid + t * 256;
                int m = fidx >> 3, kq = fidx & 7;
                int row = m0 + m;
                float4 v = make_float4(0.f, 0.f, 0.f, 0.f);
                if (row < N_PROD) v = *(const float4*)&A[row * 128 + kc0 + kq * 4];
                As[kq * 4 + 0][m] = v.x;
                As[kq * 4 + 1][m] = v.y;
                As[kq * 4 + 2][m] = v.z;
                As[kq * 4 + 3][m] = v.w;
            }
            // load B tile: 32x128 floats = 1024 float4, 4 per thread
#pragma unroll
            for (int t = 0; t < 4; t++) {
                int fidx = tid + t * 256;
                int kk = fidx >> 5, nq = fidx & 31;
                *(float4*)&Bs[kk][nq * 4] = *(const float4*)&B[(kc0 + kk) * 128 + nq * 4];
            }
            __syncthreads();
#pragma unroll
            for (int kk = 0; kk < 32; kk++) {
                float4 a4 = *(const float4*)&As[kk][ty * 4];
                float4 b4a = *(const float4*)&Bs[kk][tx * 8];
                float4 b4b = *(const float4*)&Bs[kk][tx * 8 + 4];
                unsigned long long av2[4], bv2[4];
                av2[0] = pack2(a4.x, a4.x);
                av2[1] = pack2(a4.y, a4.y);
                av2[2] = pack2(a4.z, a4.z);
                av2[3] = pack2(a4.w, a4.w);
                bv2[0] = pack2(b4a.x, b4a.y);
                bv2[1] = pack2(b4a.z, b4a.w);
                bv2[2] = pack2(b4b.x, b4b.y);
                bv2[3] = pack2(b4b.z, b4b.w);
#pragma unroll
                for (int i = 0; i < 4; i++)
#pragma unroll
                    for (int j = 0; j < 4; j++) ffma2(acc[i][j], av2[i], bv2[j]);
            }
            __syncthreads();
        }
    }

    // Stage B (smem aliased; stage A ended with a barrier)
    float (*Rs)[129] = (float (*)[129])sbuf;             // 64x129x4 = 33024 B
    float (*Bs2)[64] = (float (*)[64])(sbuf + 33024);    // 16x64x4 = 4096 B
#pragma unroll
    for (int i = 0; i < 4; i++) {
        int m = ty * 4 + i;
#pragma unroll
        for (int j = 0; j < 4; j++) {
            int c = tx * 8 + j * 2;
            float lo, hi;
            unpack2(acc[i][j], lo, hi);
            float v0 = lo + g_bias[c];
            float v1 = hi + g_bias[c + 1];
            Rs[m][c] = (v0 > 0.f) ? v0 : 0.f;
            Rs[m][c + 1] = (v1 > 0.f) ? v1 : 0.f;
        }
    }
    __syncthreads();

    float acc2[4][4];
#pragma unroll
    for (int i = 0; i < 4; i++)
#pragma unroll
        for (int j = 0; j < 4; j++) acc2[i][j] = 0.f;

    for (int kt = 0; kt < 8; kt++) {
#pragma unroll
        for (int t = 0; t < 4; t++) {
            int idx = tid + t * 256;
            int kk = idx >> 6, n = idx & 63;
            Bs2[kk][n] = Wout[(kt * 16 + kk) * 64 + n];
        }
        __syncthreads();
#pragma unroll
        for (int kk = 0; kk < 16; kk++) {
            float av[4], bv[4];
#pragma unroll
            for (int i = 0; i < 4; i++) av[i] = Rs[ty * 4 + i][kt * 16 + kk];
#pragma unroll
            for (int j = 0; j < 4; j++) bv[j] = Bs2[kk][tx * 4 + j];
#pragma unroll
            for (int i = 0; i < 4; i++)
#pragma unroll
                for (int j = 0; j < 4; j++) acc2[i][j] += av[i] * bv[j];
        }
        __syncthreads();
    }
#pragma unroll
    for (int i = 0; i < 4; i++) {
        int row = m0 + ty * 4 + i;
        if (row < N_PROD) {
#pragma unroll
            for (int j = 0; j < 4; j++) {
                int c = tx * 4 + j;
                out[row * 64 + c] = acc2[i][j] + bout[c];
            }
        }
    }
}

// ------------------------- launch -------------------------
extern "C" void kernel_launch(void* const* d_in, const int* in_sizes, int n_in,
                              void* d_out, int out_size) {
    const float* x_cust = (const float*)d_in[0];
    const float* x_prod = (const float*)d_in[1];
    EdgePtrs ep;
    for (int r = 0; r < NREL; r++) {
        ep.src[r] = (const int*)d_in[2 + 2 * r];
        ep.dst[r] = (const int*)d_in[3 + 2 * r];
    }
    ep.E = in_sizes[2];
    const float* W_gcn  = (const float*)d_in[12];
    const float* b_gcn  = (const float*)d_in[13];
    const float* Ws_gat = (const float*)d_in[14];
    const float* Wd_gat = (const float*)d_in[15];
    const float* a_s    = (const float*)d_in[16];
    const float* a_d    = (const float*)d_in[17];
    const float* b_gat  = (const float*)d_in[18];
    const float* Wl_to  = (const float*)d_in[19];
    const float* b_to   = (const float*)d_in[20];
    const float* Wr_to  = (const float*)d_in[21];
    const float* Wl_fr  = (const float*)d_in[22];
    const float* b_fr   = (const float*)d_in[23];
    const float* Wr_fr  = (const float*)d_in[24];
    const float* Wl_dv  = (const float*)d_in[25];
    const float* b_dv   = (const float*)d_in[26];
    const float* Wr_dv  = (const float*)d_in[27];
    const float* W_out  = (const float*)d_in[28];
    const float* b_out  = (const float*)d_in[29];

    setup_kernel<<<321, 256>>>(Ws_gat, Wd_gat, a_s, a_d,
                               b_gcn, b_gat, b_to, b_fr, b_dv,
                               Wr_to, Wr_fr, Wr_dv);
    phase1_kernel<<<ROWDOT_BLOCKS + 6 * 256, 256>>>(x_cust, x_prod, ep);

    dim3 sgrid32(32, 5);
    scan_p1<<<sgrid32, 320>>>();
    scan_p2<<<sgrid32, 320>>>();
    dim3 sgrid(256, 5);
    scatter_all<<<sgrid, 256>>>(ep);

    dim3 agrid((N_PROD + 7) / 8, 5);
    agg_all<<<agrid, 256>>>();

    gemm_fused<<<(N_PROD + 63) / 64, 256>>>(x_prod, W_gcn, Ws_gat, Wl_to, Wl_fr, Wl_dv,
                                            W_out, b_out, (float*)d_out);
}